// round 9
// baseline (speedup 1.0000x reference)
#include <cuda_runtime.h>

// InducingLocationsSpatialTransform: bilinear affine warp
// X: (N=512, H=64, W=64, C=32) f32, theta: (N, 6) f32 -> out: (N,H,W,C) f32
//
// One warp per 32 consecutive pixels (same image, same grid row).
// Phase 1: lane j computes pixel j's params, compressed to ONE float4:
//          { off_code = offA | dx | (dy<<1), px, py, - }  (offA multiple of 32)
//          Weights reconstruct as: qx = dx - px, qy = dy - py,
//          wa=px*py wb=px*qy wc=qx*py wd=qx*qy  (clipped-corner semantics).
// Phase 2: software-pipelined loop: prefetch params j+1 (LDS.128 broadcast)
//          while gathering pixel j with 4 scalar LDG.32 (one 128B line each),
//          blend, streaming store. 6 L1 wavefronts per pixel total.

#define N_ 512
#define H_ 64
#define W_ 64
#define C_ 32
#define HW_ (H_ * W_)

__global__ __launch_bounds__(256, 6) void st_kernel(
    const float* __restrict__ X,
    const float* __restrict__ theta,
    float* __restrict__ out)
{
    __shared__ float4 sp[8][32];

    int lane  = threadIdx.x & 31;
    int wid   = threadIdx.x >> 5;
    int gwarp = blockIdx.x * 8 + wid;
    int wbase = gwarp << 5;            // first pixel of this warp's batch

    int n  = wbase >> 12;              // image index (same for all 32 pixels)
    int p0 = wbase & 4095;
    int y  = p0 >> 6;                  // grid row (same for all 32 pixels)
    int x  = (p0 & 63) + lane;         // lane's pixel column

    const float* th = theta + n * 6;
    float t0 = __ldg(th + 0), t1 = __ldg(th + 1), t2 = __ldg(th + 2);
    float t3 = __ldg(th + 3), t4 = __ldg(th + 4), t5 = __ldg(th + 5);

    // ---- Phase 1: per-lane pixel math (pixel wbase+lane) ----
    const float step = 2.0f / 63.0f;
    float xt = -1.0f + (float)x * step;
    float yt = -1.0f + (float)y * step;

    float gx = (float)W_ * ((t0 * xt + t1 * yt + t2) + 1.0f) * 0.5f;
    float gy = (float)H_ * ((t3 * xt + t4 * yt + t5) + 1.0f) * 0.5f;

    float fx = floorf(gx), fy = floorf(gy);
    int x0 = min(max((int)fx,     0), W_ - 1);
    int x1 = min(max((int)fx + 1, 0), W_ - 1);
    int y0 = min(max((int)fy,     0), H_ - 1);
    int y1 = min(max((int)fy + 1, 0), H_ - 1);

    float px = (float)x1 - gx;         // wa = px*py, wb = px*qy
    float py = (float)y1 - gy;         // wc = qx*py, wd = qx*qy
    // qx = (x1-x0) - px, qy = (y1-y0) - py  (reconstructed in phase 2)

    int off_code = (y0 * (W_ * C_) + x0 * C_)   // multiple of 32
                 | (x1 - x0)                    // bit 0
                 | ((y1 - y0) << 1);            // bit 1

    sp[wid][lane] = make_float4(__int_as_float(off_code), px, py, 0.0f);
    __syncwarp();

    // ---- Phase 2: pipelined gather/blend; every LDG hits one 128B line ----
    const float* Sn = X + (size_t)n * (HW_ * C_) + lane;
    float*       On = out + (size_t)wbase * C_ + lane;

    float4 pj = sp[wid][0];
    #pragma unroll
    for (int j = 0; j < 32; j++) {
        float4 pn = sp[wid][(j + 1) & 31];   // prefetch next params (broadcast)

        int oc   = __float_as_int(pj.x);
        int base = oc & 0x7FFFFFE0;
        int dxb  = oc & 1;
        int dyb  = (oc >> 1) & 1;
        int dxo  = dxb << 5;                 // 0 or 32 floats
        int dyo  = dyb << 11;                // 0 or 2048 floats

        const float* bp = Sn + base;
        float va = __ldg(bp);
        float vb = __ldg(bp + dyo);
        float vc = __ldg(bp + dxo);
        float vd = __ldg(bp + dxo + dyo);

        float Px = pj.y, Py = pj.z;
        float Qx = (float)dxb - Px;
        float Qy = (float)dyb - Py;

        float r = (Px * Py) * va + (Px * Qy) * vb
                + (Qx * Py) * vc + (Qx * Qy) * vd;
        __stcs(&On[j * C_], r);              // streaming store (evict-first)

        pj = pn;
    }
}

extern "C" void kernel_launch(void* const* d_in, const int* in_sizes, int n_in,
                              void* d_out, int out_size)
{
    const float* X     = (const float*)d_in[0];
    const float* theta = (const float*)d_in[1];
    float* out         = (float*)d_out;

    // warps total = N*HW/32 = 65536; 8 warps per 256-thread block
    int blocks = (N_ * HW_) / 32 / 8;   // 8192
    st_kernel<<<blocks, 256>>>(X, theta, out);
}

// round 10
// speedup vs baseline: 1.5155x; 1.5155x over previous
#include <cuda_runtime.h>

// InducingLocationsSpatialTransform: bilinear affine warp
// X: (N=512, H=64, W=64, C=32) f32, theta: (N, 6) f32 -> out: (N,H,W,C) f32
//
// R4 structure (8 lanes/pixel, float4 loads at the 5-wavefront/pixel floor)
// extended to 4 adjacent pixels per thread (incremental affine), processed
// as two R4-style pairs. 512-thread CTAs at <=32 regs keep 2048 thr/SM while
// halving CTAs/SM (oe 8->4) to cut cross-CTA L1tex-queue contention spread.

#define N_ 512
#define H_ 64
#define W_ 64
#define C_ 32
#define HW_ (H_ * W_)

__global__ __launch_bounds__(512, 4) void st_kernel(
    const float* __restrict__ X,
    const float* __restrict__ theta,
    float* __restrict__ out)
{
    int tid = blockIdx.x * 512 + threadIdx.x;
    int q   = tid >> 3;        // 4-pixel group id
    int cg  = tid & 7;         // float4 group within the 32 channels

    int pid0 = q << 2;         // first pixel of the group
    int n = pid0 >> 12;        // image index (same for all 4 pixels)
    int p = pid0 & 4095;
    int y = p >> 6;
    int x = p & 63;            // multiple of 4; x..x+3 in same row

    const float* th = theta + n * 6;
    float t0 = __ldg(th + 0), t1 = __ldg(th + 1), t2 = __ldg(th + 2);
    float t3 = __ldg(th + 3), t4 = __ldg(th + 4), t5 = __ldg(th + 5);

    const float step = 2.0f / 63.0f;
    float xt = -1.0f + (float)x * step;
    float yt = -1.0f + (float)y * step;

    float gx0 = (float)W_ * ((t0 * xt + t1 * yt + t2) + 1.0f) * 0.5f;
    float gy0 = (float)H_ * ((t3 * xt + t4 * yt + t5) + 1.0f) * 0.5f;
    float dgx = (0.5f * (float)W_ * step) * t0;   // per-pixel x-step in source coords
    float dgy = (0.5f * (float)H_ * step) * t3;

    const float4* S = (const float4*)(X + (size_t)n * (HW_ * C_));
    float4* O = (float4*)out + (size_t)pid0 * 8;

    #pragma unroll
    for (int k = 0; k < 4; k += 2) {
        float gxa = gx0 + (float)k * dgx;
        float gya = gy0 + (float)k * dgy;
        float gxb = gxa + dgx;
        float gyb = gya + dgy;

        // ---- corner indices ----
        float fxa = floorf(gxa), fya = floorf(gya);
        float fxb = floorf(gxb), fyb = floorf(gyb);
        int ax0 = min(max((int)fxa,     0), W_ - 1);
        int ax1 = min(max((int)fxa + 1, 0), W_ - 1);
        int ay0 = min(max((int)fya,     0), H_ - 1);
        int ay1 = min(max((int)fya + 1, 0), H_ - 1);
        int bx0 = min(max((int)fxb,     0), W_ - 1);
        int bx1 = min(max((int)fxb + 1, 0), W_ - 1);
        int by0 = min(max((int)fyb,     0), H_ - 1);
        int by1 = min(max((int)fyb + 1, 0), H_ - 1);

        // ---- 8 independent full-line loads ----
        float4 va0 = __ldg(&S[(ay0 * W_ + ax0) * 8 + cg]);
        float4 vb0 = __ldg(&S[(ay1 * W_ + ax0) * 8 + cg]);
        float4 vc0 = __ldg(&S[(ay0 * W_ + ax1) * 8 + cg]);
        float4 vd0 = __ldg(&S[(ay1 * W_ + ax1) * 8 + cg]);
        float4 va1 = __ldg(&S[(by0 * W_ + bx0) * 8 + cg]);
        float4 vb1 = __ldg(&S[(by1 * W_ + bx0) * 8 + cg]);
        float4 vc1 = __ldg(&S[(by0 * W_ + bx1) * 8 + cg]);
        float4 vd1 = __ldg(&S[(by1 * W_ + bx1) * 8 + cg]);

        // ---- weights (clipped-corner semantics), in the load shadow ----
        float wa0 = ((float)ax1 - gxa) * ((float)ay1 - gya);
        float wb0 = ((float)ax1 - gxa) * (gya - (float)ay0);
        float wc0 = (gxa - (float)ax0) * ((float)ay1 - gya);
        float wd0 = (gxa - (float)ax0) * (gya - (float)ay0);
        float wa1 = ((float)bx1 - gxb) * ((float)by1 - gyb);
        float wb1 = ((float)bx1 - gxb) * (gyb - (float)by0);
        float wc1 = (gxb - (float)bx0) * ((float)by1 - gyb);
        float wd1 = (gxb - (float)bx0) * (gyb - (float)by0);

        float4 r0, r1;
        r0.x = wa0 * va0.x + wb0 * vb0.x + wc0 * vc0.x + wd0 * vd0.x;
        r0.y = wa0 * va0.y + wb0 * vb0.y + wc0 * vc0.y + wd0 * vd0.y;
        r0.z = wa0 * va0.z + wb0 * vb0.z + wc0 * vc0.z + wd0 * vd0.z;
        r0.w = wa0 * va0.w + wb0 * vb0.w + wc0 * vc0.w + wd0 * vd0.w;
        r1.x = wa1 * va1.x + wb1 * vb1.x + wc1 * vc1.x + wd1 * vd1.x;
        r1.y = wa1 * va1.y + wb1 * vb1.y + wc1 * vc1.y + wd1 * vd1.y;
        r1.z = wa1 * va1.z + wb1 * vb1.z + wc1 * vc1.z + wd1 * vd1.z;
        r1.w = wa1 * va1.w + wb1 * vb1.w + wc1 * vc1.w + wd1 * vd1.w;

        O[k * 8 + cg]       = r0;
        O[(k + 1) * 8 + cg] = r1;
    }
}

extern "C" void kernel_launch(void* const* d_in, const int* in_sizes, int n_in,
                              void* d_out, int out_size)
{
    const float* X     = (const float*)d_in[0];
    const float* theta = (const float*)d_in[1];
    float* out         = (float*)d_out;

    // total threads = N*HW*8/4 = 4,194,304
    int threads = 512;
    int blocks = (N_ * HW_ * 2) / threads;   // 8192
    st_kernel<<<blocks, threads>>>(X, theta, out);
}

// round 11
// speedup vs baseline: 1.5451x; 1.0195x over previous
#include <cuda_runtime.h>

// InducingLocationsSpatialTransform: bilinear affine warp
// X: (N=512, H=64, W=64, C=32) f32, theta: (N, 6) f32 -> out: (N,H,W,C) f32
//
// R10 structure (8 lanes/pixel float4 loads at the 5-wavefront/pixel floor,
// 4 adjacent pixels per thread) made PERSISTENT: grid = 592 CTAs (one wave
// on 148 SMs at 4 CTAs/SM), grid-stride over the 8192 virtual tiles. Kills
// 13 wave transitions (~2360 cyc each) and keeps L1 warm across tiles.

#define N_ 512
#define H_ 64
#define W_ 64
#define C_ 32
#define HW_ (H_ * W_)
#define VBLOCKS 8192          // virtual 512-thread tiles covering the output

__global__ __launch_bounds__(512, 4) void st_kernel(
    const float* __restrict__ X,
    const float* __restrict__ theta,
    float* __restrict__ out)
{
    for (int vb = blockIdx.x; vb < VBLOCKS; vb += gridDim.x) {
        int tid = vb * 512 + threadIdx.x;
        int q   = tid >> 3;        // 4-pixel group id
        int cg  = tid & 7;         // float4 group within the 32 channels

        int pid0 = q << 2;         // first pixel of the group
        int n = pid0 >> 12;        // image index (same for all 4 pixels)
        int p = pid0 & 4095;
        int y = p >> 6;
        int x = p & 63;            // multiple of 4

        const float* th = theta + n * 6;
        float t0 = __ldg(th + 0), t1 = __ldg(th + 1), t2 = __ldg(th + 2);
        float t3 = __ldg(th + 3), t4 = __ldg(th + 4), t5 = __ldg(th + 5);

        const float step = 2.0f / 63.0f;
        float xt = -1.0f + (float)x * step;
        float yt = -1.0f + (float)y * step;

        float gx0 = (float)W_ * ((t0 * xt + t1 * yt + t2) + 1.0f) * 0.5f;
        float gy0 = (float)H_ * ((t3 * xt + t4 * yt + t5) + 1.0f) * 0.5f;
        float dgx = (0.5f * (float)W_ * step) * t0;
        float dgy = (0.5f * (float)H_ * step) * t3;

        const float4* S = (const float4*)(X + (size_t)n * (HW_ * C_));
        float4* O = (float4*)out + (size_t)pid0 * 8;

        #pragma unroll
        for (int k = 0; k < 4; k += 2) {
            float gxa = gx0 + (float)k * dgx;
            float gya = gy0 + (float)k * dgy;
            float gxb = gxa + dgx;
            float gyb = gya + dgy;

            float fxa = floorf(gxa), fya = floorf(gya);
            float fxb = floorf(gxb), fyb = floorf(gyb);
            int ax0 = min(max((int)fxa,     0), W_ - 1);
            int ax1 = min(max((int)fxa + 1, 0), W_ - 1);
            int ay0 = min(max((int)fya,     0), H_ - 1);
            int ay1 = min(max((int)fya + 1, 0), H_ - 1);
            int bx0 = min(max((int)fxb,     0), W_ - 1);
            int bx1 = min(max((int)fxb + 1, 0), W_ - 1);
            int by0 = min(max((int)fyb,     0), H_ - 1);
            int by1 = min(max((int)fyb + 1, 0), H_ - 1);

            float4 va0 = __ldg(&S[(ay0 * W_ + ax0) * 8 + cg]);
            float4 vb0 = __ldg(&S[(ay1 * W_ + ax0) * 8 + cg]);
            float4 vc0 = __ldg(&S[(ay0 * W_ + ax1) * 8 + cg]);
            float4 vd0 = __ldg(&S[(ay1 * W_ + ax1) * 8 + cg]);
            float4 va1 = __ldg(&S[(by0 * W_ + bx0) * 8 + cg]);
            float4 vb1 = __ldg(&S[(by1 * W_ + bx0) * 8 + cg]);
            float4 vc1 = __ldg(&S[(by0 * W_ + bx1) * 8 + cg]);
            float4 vd1 = __ldg(&S[(by1 * W_ + bx1) * 8 + cg]);

            float wa0 = ((float)ax1 - gxa) * ((float)ay1 - gya);
            float wb0 = ((float)ax1 - gxa) * (gya - (float)ay0);
            float wc0 = (gxa - (float)ax0) * ((float)ay1 - gya);
            float wd0 = (gxa - (float)ax0) * (gya - (float)ay0);
            float wa1 = ((float)bx1 - gxb) * ((float)by1 - gyb);
            float wb1 = ((float)bx1 - gxb) * (gyb - (float)by0);
            float wc1 = (gxb - (float)bx0) * ((float)by1 - gyb);
            float wd1 = (gxb - (float)bx0) * (gyb - (float)by0);

            float4 r0, r1;
            r0.x = wa0 * va0.x + wb0 * vb0.x + wc0 * vc0.x + wd0 * vd0.x;
            r0.y = wa0 * va0.y + wb0 * vb0.y + wc0 * vc0.y + wd0 * vd0.y;
            r0.z = wa0 * va0.z + wb0 * vb0.z + wc0 * vc0.z + wd0 * vd0.z;
            r0.w = wa0 * va0.w + wb0 * vb0.w + wc0 * vc0.w + wd0 * vd0.w;
            r1.x = wa1 * va1.x + wb1 * vb1.x + wc1 * vc1.x + wd1 * vd1.x;
            r1.y = wa1 * va1.y + wb1 * vb1.y + wc1 * vc1.y + wd1 * vd1.y;
            r1.z = wa1 * va1.z + wb1 * vb1.z + wc1 * vc1.z + wd1 * vd1.z;
            r1.w = wa1 * va1.w + wb1 * vb1.w + wc1 * vc1.w + wd1 * vd1.w;

            O[k * 8 + cg]       = r0;
            O[(k + 1) * 8 + cg] = r1;
        }
    }
}

extern "C" void kernel_launch(void* const* d_in, const int* in_sizes, int n_in,
                              void* d_out, int out_size)
{
    const float* X     = (const float*)d_in[0];
    const float* theta = (const float*)d_in[1];
    float* out         = (float*)d_out;

    // one wave: 148 SMs x 4 CTAs
    st_kernel<<<592, 512>>>(X, theta, out);
}